// round 14
// baseline (speedup 1.0000x reference)
#include <cuda_runtime.h>

// Inputs (metadata order):
// 0: dist_mat   float32  [4096*4096]
// 1: vector_mat float32  [4096*4096*3]
// 2: forces_out float32  [4096*3]
// 3: params     float32  [N_ANGLES*2]  (k0, theta0)
// 4: coord_idx  int32    [N_ANGLES*3]  (a1, a2, a3)
// 5: calc_energy int32   [1]
// 6: calc_forces int32   [1]
// Output: out[0] = energy, out[1 .. 1+3*N_ATOMS) = forces

#define TPB 256            // threads per block, 1 angle per thread
#define MAX_ATOMS 4096

// Padded per-atom force accumulator: one 16B slot per atom -> every scatter is
// a single aligned red.v4. Zero at load; the last-done block re-zeros it after
// folding, so every kernel_launch invocation sees it zeroed on entry.
__device__ float4       g_scratch[MAX_ATOMS];
__device__ float        g_energy;   // energy accumulator, same lifecycle
__device__ unsigned int g_count;    // completed-block counter, same lifecycle

// L2 policy registers.
__device__ __forceinline__ unsigned long long make_evict_last_policy() {
    unsigned long long pol;
    asm("createpolicy.fractional.L2::evict_last.b64 %0, 1.0;" : "=l"(pol));
    return pol;
}
__device__ __forceinline__ unsigned long long make_evict_first_policy() {
    unsigned long long pol;
    asm("createpolicy.fractional.L2::evict_first.b64 %0, 1.0;" : "=l"(pol));
    return pol;
}

// dist: 64MB, fits in L2 -> pin with evict_last (persists across graph replays).
__device__ __forceinline__ float ldg_dist(const float* p, unsigned long long pol) {
    float v;
    asm volatile("ld.global.nc.L2::cache_hint.f32 %0, [%1], %2;"
                 : "=f"(v) : "l"(p), "l"(pol));
    return v;
}

// vec: 192MB, ~zero reuse -> evict_first so it never displaces dist/idx/params.
__device__ __forceinline__ float2 ldg_v2_ef(const float* p, unsigned long long pol) {
    float2 v;
    asm volatile("ld.global.nc.L2::cache_hint.v2.f32 {%0, %1}, [%2], %3;"
                 : "=f"(v.x), "=f"(v.y) : "l"(p), "l"(pol));
    return v;
}

// Branchless 12B gather of vec row r via two 8B-aligned float2 loads.
__device__ __forceinline__ void load_vec3(const float* __restrict__ vec, size_t r,
                                          unsigned long long pol,
                                          float& x, float& y, float& z) {
    const int odd = (int)(r & 1);
    const float2 lo = ldg_v2_ef(vec + 3 * r - odd, pol);
    const float2 hi = ldg_v2_ef(vec + 3 * r + 2 - odd, pol);
    x = odd ? lo.y : lo.x;
    y = odd ? hi.x : lo.y;
    z = odd ? hi.y : hi.x;
}

// One aligned 16B RED per atom into the padded scratch accumulator.
__device__ __forceinline__ void red_force3(int a, float fx, float fy, float fz) {
    asm volatile("red.global.add.v4.f32 [%0], {%1, %2, %3, %4};"
                 :: "l"(&g_scratch[a]), "f"(fx), "f"(fy), "f"(fz), "f"(0.f)
                 : "memory");
}

__global__ void __launch_bounds__(TPB) angle_kernel(
    const float* __restrict__ dist,
    const float* __restrict__ vec,
    const float* __restrict__ params,
    const int*   __restrict__ cidx,
    const int*   __restrict__ calc_e_p,
    const int*   __restrict__ calc_f_p,
    const float* __restrict__ forces_in,
    float*       __restrict__ out,
    int n_angles, int n_atoms)
{
    const int j  = blockIdx.x * blockDim.x + threadIdx.x;
    const int ce = __ldg(calc_e_p);
    const int cf = __ldg(calc_f_p);
    float e = 0.0f;

    if (j < n_angles) {
        const unsigned long long pol_last  = make_evict_last_policy();
        const unsigned long long pol_first = make_evict_first_policy();

        // Indices: 12B at cidx+3j, parity trick (two 8B loads, coalesced).
        const int jodd = j & 1;
        const int2 clo = *(const int2*)(cidx + 3 * j - jodd);
        const int2 chi = *(const int2*)(cidx + 3 * j + 2 - jodd);
        const int a1 = jodd ? clo.y : clo.x;
        const int a2 = jodd ? chi.x : clo.y;
        const int a3 = jodd ? chi.y : chi.x;

        // Params: 8B aligned always.
        const float2 p = *(const float2*)(params + 2 * j);
        const float k0 = p.x, t0 = p.y;

        const size_t r21 = (size_t)a2 * (size_t)n_atoms + (size_t)a1;
        const size_t r23 = (size_t)a2 * (size_t)n_atoms + (size_t)a3;

        // Front-batched gathers; dist (L2-resident) first, vec behind it.
        const float d21 = ldg_dist(dist + r21, pol_last);
        const float d23 = ldg_dist(dist + r23, pol_last);
        float v21x, v21y, v21z, v23x, v23y, v23z;
        load_vec3(vec, r21, pol_first, v21x, v21y, v21z);
        load_vec3(vec, r23, pol_first, v23x, v23y, v23z);

        float ct = v21x * v23x + v21y * v23y + v21z * v23z;
        ct = fminf(1.0f, fmaxf(-1.0f, ct));

        const float theta = acosf(ct);
        const float dth   = theta - t0;

        e = k0 * dth * dth;

        if (cf) {
            const float st   = sqrtf(fmaxf(0.0f, 1.0f - ct * ct));
            const float coef = (st > 0.0f)
                             ? (-2.0f * k0 * dth / fmaxf(st, 1e-12f))
                             : 0.0f;
            const float c21 = coef / d21;
            const float c23 = coef / d23;

            const float f0x = c21 * (ct * v21x - v23x);
            const float f0y = c21 * (ct * v21y - v23y);
            const float f0z = c21 * (ct * v21z - v23z);
            const float f2x = c23 * (ct * v23x - v21x);
            const float f2y = c23 * (ct * v23y - v21y);
            const float f2z = c23 * (ct * v23z - v21z);

            red_force3(a1, f0x, f0y, f0z);
            red_force3(a2, -(f0x + f2x), -(f0y + f2y), -(f0z + f2z));
            red_force3(a3, f2x, f2y, f2z);
        }
    }

    // Energy reduction into g_energy: warp shuffle -> shared -> atomic/block.
    if (ce) {
        #pragma unroll
        for (int off = 16; off > 0; off >>= 1)
            e += __shfl_down_sync(0xffffffffu, e, off);

        __shared__ float warp_sums[TPB / 32];
        const int lane = threadIdx.x & 31;
        const int wid  = threadIdx.x >> 5;
        if (lane == 0) warp_sums[wid] = e;
        __syncthreads();

        if (wid == 0) {
            e = (lane < TPB / 32) ? warp_sums[lane] : 0.0f;
            #pragma unroll
            for (int off = (TPB / 64); off > 0; off >>= 1)
                e += __shfl_down_sync(0xffffffffu, e, off);
            if (lane == 0) atomicAdd(&g_energy, e);
        }
    }

    // ---- Last-block-done fold (threadFenceReduction pattern) ----
    __shared__ bool is_last;
    __syncthreads();                 // all block REDs/atomics issued
    if (threadIdx.x == 0) {
        __threadfence();             // make this block's REDs device-visible
        const unsigned int done = atomicAdd(&g_count, 1u);
        is_last = (done == gridDim.x - 1);
    }
    __syncthreads();

    if (is_last) {
        __threadfence();             // acquire: all blocks' REDs now visible
        for (int a = threadIdx.x; a < n_atoms; a += TPB) {
            const float4 s = g_scratch[a];
            out[1 + 3 * a + 0] = forces_in[3 * a + 0] + s.x;
            out[1 + 3 * a + 1] = forces_in[3 * a + 1] + s.y;
            out[1 + 3 * a + 2] = forces_in[3 * a + 2] + s.z;
            g_scratch[a] = make_float4(0.f, 0.f, 0.f, 0.f);
        }
        if (threadIdx.x == 0) {
            out[0]   = g_energy;
            g_energy = 0.0f;
            g_count  = 0u;           // reset for next (graph-replayed) launch
        }
    }
}

extern "C" void kernel_launch(void* const* d_in, const int* in_sizes, int n_in,
                              void* d_out, int out_size) {
    const float* dist   = (const float*)d_in[0];
    const float* vec    = (const float*)d_in[1];
    const float* f_in   = (const float*)d_in[2];
    const float* params = (const float*)d_in[3];
    const int*   cidx   = (const int*)  d_in[4];
    const int*   ce     = (const int*)  d_in[5];
    const int*   cf     = (const int*)  d_in[6];
    float*       out    = (float*)d_out;

    const int n_angles = in_sizes[4] / 3;
    const int n_forces = in_sizes[2];
    const int n_atoms  = n_forces / 3;

    const int blocks = (n_angles + TPB - 1) / TPB;
    angle_kernel<<<blocks, TPB>>>(dist, vec, params, cidx, ce, cf,
                                  f_in, out, n_angles, n_atoms);
}

// round 15
// speedup vs baseline: 1.3321x; 1.3321x over previous
#include <cuda_runtime.h>

// Inputs (metadata order):
// 0: dist_mat   float32  [4096*4096]
// 1: vector_mat float32  [4096*4096*3]
// 2: forces_out float32  [4096*3]
// 3: params     float32  [N_ANGLES*2]  (k0, theta0)
// 4: coord_idx  int32    [N_ANGLES*3]  (a1, a2, a3)
// 5: calc_energy int32   [1]
// 6: calc_forces int32   [1]
// Output: out[0] = energy, out[1 .. 1+3*N_ATOMS) = forces

#define TPB 256            // threads per block, 1 angle per thread
#define MAX_ATOMS 4096

// Padded per-atom force accumulator: one 16B slot per atom -> every scatter is
// a single aligned red.v4. Zero-initialized at load; fold_kernel re-zeros it,
// so every kernel_launch invocation sees it zeroed on entry (deterministic).
__device__ float4 g_scratch[MAX_ATOMS];
// Energy accumulator, same lifecycle (zero at entry, re-zeroed by fold).
__device__ float  g_energy;

// Fold: out-forces = forces_in + scratch; out-energy = g_energy.
// Launched with PDL: its prologue overlaps the angle kernel's drain tail;
// cudaGridDependencySynchronize() guarantees all angle REDs are visible.
__global__ void fold_kernel(float* __restrict__ out,
                            const float* __restrict__ forces_in,
                            int n_atoms) {
    cudaGridDependencySynchronize();
    int a = blockIdx.x * blockDim.x + threadIdx.x;
    if (a < n_atoms) {
        const float4 s = g_scratch[a];
        out[1 + 3 * a + 0] = forces_in[3 * a + 0] + s.x;
        out[1 + 3 * a + 1] = forces_in[3 * a + 1] + s.y;
        out[1 + 3 * a + 2] = forces_in[3 * a + 2] + s.z;
        g_scratch[a] = make_float4(0.f, 0.f, 0.f, 0.f);
    }
    if (a == 0) {
        out[0]   = g_energy;
        g_energy = 0.0f;
    }
}

// L2 policy registers.
__device__ __forceinline__ unsigned long long make_evict_last_policy() {
    unsigned long long pol;
    asm("createpolicy.fractional.L2::evict_last.b64 %0, 1.0;" : "=l"(pol));
    return pol;
}
__device__ __forceinline__ unsigned long long make_evict_first_policy() {
    unsigned long long pol;
    asm("createpolicy.fractional.L2::evict_first.b64 %0, 1.0;" : "=l"(pol));
    return pol;
}

// dist: 64MB, fits in L2 -> pin with evict_last (persists across graph replays).
__device__ __forceinline__ float ldg_dist(const float* p, unsigned long long pol) {
    float v;
    asm volatile("ld.global.nc.L2::cache_hint.f32 %0, [%1], %2;"
                 : "=f"(v) : "l"(p), "l"(pol));
    return v;
}

// vec: 192MB, ~zero reuse -> evict_first so it never displaces dist/idx/params.
__device__ __forceinline__ float2 ldg_v2_ef(const float* p, unsigned long long pol) {
    float2 v;
    asm volatile("ld.global.nc.L2::cache_hint.v2.f32 {%0, %1}, [%2], %3;"
                 : "=f"(v.x), "=f"(v.y) : "l"(p), "l"(pol));
    return v;
}

// Branchless 12B gather of vec row r via two 8B-aligned float2 loads.
__device__ __forceinline__ void load_vec3(const float* __restrict__ vec, size_t r,
                                          unsigned long long pol,
                                          float& x, float& y, float& z) {
    const int odd = (int)(r & 1);
    const float2 lo = ldg_v2_ef(vec + 3 * r - odd, pol);
    const float2 hi = ldg_v2_ef(vec + 3 * r + 2 - odd, pol);
    x = odd ? lo.y : lo.x;
    y = odd ? hi.x : lo.y;
    z = odd ? hi.y : hi.x;
}

// One aligned 16B RED per atom into the padded scratch accumulator.
// Fire-and-forget: NO fence behind these on the hot path (R13 lesson).
__device__ __forceinline__ void red_force3(int a, float fx, float fy, float fz) {
    asm volatile("red.global.add.v4.f32 [%0], {%1, %2, %3, %4};"
                 :: "l"(&g_scratch[a]), "f"(fx), "f"(fy), "f"(fz), "f"(0.f)
                 : "memory");
}

__global__ void __launch_bounds__(TPB) angle_kernel(
    const float* __restrict__ dist,
    const float* __restrict__ vec,
    const float* __restrict__ params,
    const int*   __restrict__ cidx,
    const int*   __restrict__ calc_e_p,
    const int*   __restrict__ calc_f_p,
    int n_angles, int n_atoms)
{
    const int j  = blockIdx.x * blockDim.x + threadIdx.x;
    const int ce = __ldg(calc_e_p);
    const int cf = __ldg(calc_f_p);
    float e = 0.0f;

    if (j < n_angles) {
        const unsigned long long pol_last  = make_evict_last_policy();
        const unsigned long long pol_first = make_evict_first_policy();

        // Indices: 12B at cidx+3j, parity trick (two 8B loads, coalesced).
        const int jodd = j & 1;
        const int2 clo = *(const int2*)(cidx + 3 * j - jodd);
        const int2 chi = *(const int2*)(cidx + 3 * j + 2 - jodd);
        const int a1 = jodd ? clo.y : clo.x;
        const int a2 = jodd ? chi.x : clo.y;
        const int a3 = jodd ? chi.y : chi.x;

        // Params: 8B aligned always.
        const float2 p = *(const float2*)(params + 2 * j);
        const float k0 = p.x, t0 = p.y;

        const size_t r21 = (size_t)a2 * (size_t)n_atoms + (size_t)a1;
        const size_t r23 = (size_t)a2 * (size_t)n_atoms + (size_t)a3;

        // Front-batched gathers; dist (L2-resident) first, vec behind it.
        const float d21 = ldg_dist(dist + r21, pol_last);
        const float d23 = ldg_dist(dist + r23, pol_last);
        float v21x, v21y, v21z, v23x, v23y, v23z;
        load_vec3(vec, r21, pol_first, v21x, v21y, v21z);
        load_vec3(vec, r23, pol_first, v23x, v23y, v23z);

        float ct = v21x * v23x + v21y * v23y + v21z * v23z;
        ct = fminf(1.0f, fmaxf(-1.0f, ct));

        const float theta = acosf(ct);
        const float dth   = theta - t0;

        e = k0 * dth * dth;

        if (cf) {
            const float st   = sqrtf(fmaxf(0.0f, 1.0f - ct * ct));
            const float coef = (st > 0.0f)
                             ? (-2.0f * k0 * dth / fmaxf(st, 1e-12f))
                             : 0.0f;
            const float c21 = coef / d21;
            const float c23 = coef / d23;

            const float f0x = c21 * (ct * v21x - v23x);
            const float f0y = c21 * (ct * v21y - v23y);
            const float f0z = c21 * (ct * v21z - v23z);
            const float f2x = c23 * (ct * v23x - v21x);
            const float f2y = c23 * (ct * v23y - v21y);
            const float f2z = c23 * (ct * v23z - v21z);

            red_force3(a1, f0x, f0y, f0z);
            red_force3(a2, -(f0x + f2x), -(f0y + f2y), -(f0z + f2z));
            red_force3(a3, f2x, f2y, f2z);
        }
    }

    // Hierarchical energy reduction into g_energy: shuffle -> shared -> atomic.
    if (ce) {
        #pragma unroll
        for (int off = 16; off > 0; off >>= 1)
            e += __shfl_down_sync(0xffffffffu, e, off);

        __shared__ float warp_sums[TPB / 32];
        const int lane = threadIdx.x & 31;
        const int wid  = threadIdx.x >> 5;
        if (lane == 0) warp_sums[wid] = e;
        __syncthreads();

        if (wid == 0) {
            e = (lane < TPB / 32) ? warp_sums[lane] : 0.0f;
            #pragma unroll
            for (int off = (TPB / 64); off > 0; off >>= 1)
                e += __shfl_down_sync(0xffffffffu, e, off);
            if (lane == 0) atomicAdd(&g_energy, e);
        }
    }

    // Let the dependent fold kernel begin launching while we drain.
    cudaTriggerProgrammaticLaunchCompletion();
}

extern "C" void kernel_launch(void* const* d_in, const int* in_sizes, int n_in,
                              void* d_out, int out_size) {
    const float* dist   = (const float*)d_in[0];
    const float* vec    = (const float*)d_in[1];
    const float* f_in   = (const float*)d_in[2];
    const float* params = (const float*)d_in[3];
    const int*   cidx   = (const int*)  d_in[4];
    const int*   ce     = (const int*)  d_in[5];
    const int*   cf     = (const int*)  d_in[6];
    float*       out    = (float*)d_out;

    const int n_angles = in_sizes[4] / 3;
    const int n_forces = in_sizes[2];
    const int n_atoms  = n_forces / 3;

    // 1) Main: gathers + 3x aligned red.v4 into scratch + energy into g_energy.
    {
        const int blocks = (n_angles + TPB - 1) / TPB;
        angle_kernel<<<blocks, TPB>>>(dist, vec, params, cidx, ce, cf,
                                      n_angles, n_atoms);
    }

    // 2) Fold (PDL): prologue overlaps angle drain; grid-sync before reading.
    {
        const int threads = 256;
        const int blocks  = (n_atoms + threads - 1) / threads;

        cudaLaunchAttribute attrs[1];
        attrs[0].id = cudaLaunchAttributeProgrammaticStreamSerialization;
        attrs[0].val.programmaticStreamSerializationAllowed = 1;

        cudaLaunchConfig_t cfg = {};
        cfg.gridDim  = dim3((unsigned)blocks, 1, 1);
        cfg.blockDim = dim3((unsigned)threads, 1, 1);
        cfg.dynamicSmemBytes = 0;
        cfg.stream   = 0;
        cfg.attrs    = attrs;
        cfg.numAttrs = 1;

        cudaLaunchKernelEx(&cfg, fold_kernel, out, f_in, n_atoms);
    }
}